// round 8
// baseline (speedup 1.0000x reference)
#include <cuda_runtime.h>
#include <cstdint>

#define B_ 8
#define N_ 16384
#define M_ 1024
#define C_ 64
#define NS_ 32
#define COUT_ 67
#define R2_ 0.04f

#define BQ_BLOCKS ((B_ * M_) / 8)                    // 1024
#define TR_BLOCKS ((N_ / 32) * (C_ / 32) * B_)       // 8192

// Scratch: transposed features (B, N, C) = 32 MB, and ball-query indices = 1 MB.
__device__ float g_ft[(size_t)B_ * N_ * C_];
__device__ int   g_idx[(size_t)B_ * M_ * NS_];

// ---------------------------------------------------------------------------
// Phase 1 (fused): blocks [0, BQ_BLOCKS) do ball query; the rest transpose
// features. Ballquery is latency/issue-bound with ~0% DRAM; transpose is pure
// bandwidth — running them concurrently hides the transpose.
// ---------------------------------------------------------------------------

__device__ __forceinline__ void bq_load(const float* __restrict__ xb, int base,
                                        int lane, float px[4], float py[4],
                                        float pz[4]) {
#pragma unroll
    for (int g = 0; g < 4; g++) {
        const float* p = xb + (size_t)(base + g * 32 + lane) * 3;
        px[g] = p[0]; py[g] = p[1]; pz[g] = p[2];
    }
}

// Evaluate 128 points held in registers. Fast path: nibble + ONE redux.
// Placement (4 ballots) only while total < NS_ and hits exist.
// Returns true when the query is complete.
__device__ __forceinline__ bool bq_process(
    const float px[4], const float py[4], const float pz[4],
    float qx, float qy, float qz, int base, int lane, unsigned ltm,
    int* __restrict__ sidxw, int& total) {

    unsigned nib = 0u;
#pragma unroll
    for (int g = 0; g < 4; g++) {
        const float dx = px[g] - qx;
        const float dy = py[g] - qy;
        const float dz = pz[g] - qz;
        if (dx * dx + dy * dy + dz * dz < R2_) nib |= 1u << g;
    }
    const int cnt = __reduce_add_sync(0xffffffffu, __popc(nib));
    if (cnt) {
        if (total < NS_) {
            unsigned msk[4];
#pragma unroll
            for (int g = 0; g < 4; g++)
                msk[g] = __ballot_sync(0xffffffffu, (nib >> g) & 1u);
            int run = total;
#pragma unroll
            for (int g = 0; g < 4; g++) {
                if (msk[g]) {
                    const int pos = run + __popc(msk[g] & ltm);
                    if (((nib >> g) & 1u) && pos < NS_)
                        sidxw[pos] = base + g * 32 + lane;
                    run += __popc(msk[g]);
                }
            }
        }
        total += cnt;
        if (total >= NS_) return true;
    }
    return false;
}

__global__ void __launch_bounds__(256) phase1_kernel(
    const float* __restrict__ xyz, const float* __restrict__ new_xyz,
    const float* __restrict__ f) {

    if (blockIdx.x < BQ_BLOCKS) {
        // ================= ball query: one warp per query ==================
        __shared__ int sidx[8][NS_];

        const int tid  = threadIdx.x;
        const int w    = tid >> 5;
        const int lane = tid & 31;
        const int q    = blockIdx.x * 8 + w;
        const int b    = q >> 10;

        const float* xb = xyz + (size_t)b * N_ * 3;
        const float* qp = new_xyz + (size_t)q * 3;
        const float qx = qp[0], qy = qp[1], qz = qp[2];
        const unsigned ltm = (1u << lane) - 1u;

        int total = 0;
        float axp[4], ayp[4], azp[4];   // buffer A
        float bxp[4], byp[4], bzp[4];   // buffer B

        bq_load(xb, 0, lane, axp, ayp, azp);

        for (int n0 = 0; n0 < N_; n0 += 256) {
            // half 1: prefetch B(n0+128), process A(n0)
            bq_load(xb, n0 + 128, lane, bxp, byp, bzp);
            if (bq_process(axp, ayp, azp, qx, qy, qz, n0, lane, ltm,
                           sidx[w], total))
                break;

            // half 2: prefetch A(n0+256), process B(n0+128)
            if (n0 + 256 < N_)
                bq_load(xb, n0 + 256, lane, axp, ayp, azp);
            if (bq_process(bxp, byp, bzp, qx, qy, qz, n0 + 128, lane, ltm,
                           sidx[w], total))
                break;
        }

        __syncwarp();
        int v;
        if (total == 0) {
            v = N_ - 1;  // reference: all-invalid -> clamped gather
        } else {
            const int first = sidx[w][0];
            v = (lane < min(total, NS_)) ? sidx[w][lane] : first;
        }
        g_idx[(size_t)q * NS_ + lane] = v;

    } else {
        // ============ transpose features (B,C,N)->(B,N,C), float4 ==========
        __shared__ float tile[32][33];

        const int t  = blockIdx.x - BQ_BLOCKS;
        const int bx = t & 511;           // N/32 = 512
        const int by = (t >> 9) & 1;      // C/32 = 2
        const int bz = t >> 10;           // B
        const int n0 = bx * 32;
        const int c0 = by * 32;
        const int tx = threadIdx.x & 7;
        const int ty = threadIdx.x >> 3;

        const float* src = f + (size_t)bz * C_ * N_;
        float*       dst = g_ft + (size_t)bz * N_ * C_;

        const float4 v = *(const float4*)(src + (size_t)(c0 + ty) * N_ + n0 + tx * 4);
        tile[ty][tx * 4 + 0] = v.x;
        tile[ty][tx * 4 + 1] = v.y;
        tile[ty][tx * 4 + 2] = v.z;
        tile[ty][tx * 4 + 3] = v.w;
        __syncthreads();

        float4 o;
        o.x = tile[tx * 4 + 0][ty];
        o.y = tile[tx * 4 + 1][ty];
        o.z = tile[tx * 4 + 2][ty];
        o.w = tile[tx * 4 + 3][ty];
        *(float4*)(dst + (size_t)(n0 + ty) * C_ + c0 + tx * 4) = o;
    }
}

// ---------------------------------------------------------------------------
// Kernel 2: grouping. One block per (b, m). Gather stays scalar/conflict-free;
// the write loop is vectorized: 4 scalar LDS from a tile COLUMN (stride 33
// == 1 mod 32 -> conflict-free across the warp) feed one STG.128. Iterations
// per thread drop 8.375 -> 2.09.
// ---------------------------------------------------------------------------
__global__ void group_kernel(const float* __restrict__ xyz,
                             const float* __restrict__ new_xyz,
                             float* __restrict__ out) {
    __shared__ int   sidx[NS_];
    __shared__ float tile[COUT_][33];

    const int bm = blockIdx.x;
    const int b  = bm >> 10;
    const int m  = bm & (M_ - 1);
    const int t  = threadIdx.x;          // 256 threads
    const int w  = t >> 5;
    const int lane = t & 31;

    if (t < NS_) sidx[t] = g_idx[(size_t)bm * NS_ + t];
    __syncthreads();

    const float* ftb = g_ft + (size_t)b * N_ * C_;
    const float* qp  = new_xyz + ((size_t)b * M_ + m) * 3;

#pragma unroll
    for (int k = 0; k < 4; k++) {
        const int s = w + k * 8;         // 8 warps cover 32 samples
        const int n = sidx[s];
        const float* col = ftb + (size_t)n * C_;
        tile[3 + lane][s]      = col[lane];
        tile[3 + 32 + lane][s] = col[lane + 32];
        if (lane < 3)
            tile[lane][s] = xyz[((size_t)b * N_ + n) * 3 + lane] - qp[lane];
    }
    __syncthreads();

    float* ob = out + ((size_t)b * COUT_ * M_ + m) * NS_;
    // 67 channels x 8 float4 segments = 536 vector stores.
    for (int e = t; e < COUT_ * 8; e += 256) {
        const int c  = e >> 3;
        const int s4 = (e & 7) * 4;
        float4 v;
        v.x = tile[c][s4 + 0];
        v.y = tile[c][s4 + 1];
        v.z = tile[c][s4 + 2];
        v.w = tile[c][s4 + 3];
        *(float4*)(ob + (size_t)c * (M_ * NS_) + s4) = v;
    }
}

// ---------------------------------------------------------------------------
extern "C" void kernel_launch(void* const* d_in, const int* in_sizes, int n_in,
                              void* d_out, int out_size) {
    const float* xyz = nullptr;
    const float* new_xyz = nullptr;
    const float* feats = nullptr;
    for (int i = 0; i < n_in; i++) {
        if (in_sizes[i] == B_ * N_ * 3)      xyz     = (const float*)d_in[i];
        else if (in_sizes[i] == B_ * M_ * 3) new_xyz = (const float*)d_in[i];
        else if (in_sizes[i] == B_ * C_ * N_) feats  = (const float*)d_in[i];
    }
    float* out = (float*)d_out;

    phase1_kernel<<<BQ_BLOCKS + TR_BLOCKS, 256>>>(xyz, new_xyz, feats);
    group_kernel<<<B_ * M_, 256>>>(xyz, new_xyz, out);
}

// round 9
// speedup vs baseline: 1.0683x; 1.0683x over previous
#include <cuda_runtime.h>
#include <cstdint>

#define B_ 8
#define N_ 16384
#define M_ 1024
#define C_ 64
#define NS_ 32
#define COUT_ 67
#define R2_ 0.04f

#define BQ_BLOCKS ((B_ * M_) / 8)            // 1024
#define TR_BLOCKS ((N_ / 128) * (C_ / 32) * B_)  // 2048 (4 tiles/block along n)

// Scratch: transposed features (B, N, C) = 32 MB, and ball-query indices = 1 MB.
__device__ float g_ft[(size_t)B_ * N_ * C_];
__device__ int   g_idx[(size_t)B_ * M_ * NS_];

// ---------------------------------------------------------------------------
// Ball-query helpers. A 256-pt chunk is 3072 floats = 768 float4; thread t
// owns float4s [t*6, t*6+6) = floats [t*24, t*24+24) = points
// [chunk + 8t, chunk + 8t + 8) with x,y,z sequential in its own registers.
// ---------------------------------------------------------------------------
struct BqBuf { float4 f[6]; };

__device__ __forceinline__ void bq_load(const float4* __restrict__ base4,
                                        int tfo, BqBuf& b) {
#pragma unroll
    for (int k = 0; k < 6; k++) b.f[k] = base4[tfo + k];
}

// 8-bit hit mask for the thread's 8 points (bit j = point 8*lane + j).
__device__ __forceinline__ unsigned bq_mask(const BqBuf& b, float qx, float qy,
                                            float qz) {
    const float* s = (const float*)b.f;   // stays in regs (fully unrolled)
    unsigned m = 0u;
#pragma unroll
    for (int j = 0; j < 8; j++) {
        const float dx = s[3 * j + 0] - qx;
        const float dy = s[3 * j + 1] - qy;
        const float dz = s[3 * j + 2] - qz;
        if (dx * dx + dy * dy + dz * dz < R2_) m |= 1u << j;
    }
    return m;
}

// Rare path: ordered placement of this chunk's hits (order = point index =
// chunk + 8*lane + j). Exclusive warp prefix of per-thread popc via shfl scan.
__device__ __forceinline__ void bq_place(unsigned mask, int chunk, int lane,
                                         int total, int* __restrict__ sidxw) {
    const int c = __popc(mask);
    int incl = c;
#pragma unroll
    for (int d = 1; d < 32; d <<= 1) {
        const int v = __shfl_up_sync(0xffffffffu, incl, d);
        if (lane >= d) incl += v;
    }
    int pos = total + (incl - c);
#pragma unroll
    for (int j = 0; j < 8; j++) {
        if ((mask >> j) & 1u) {
            if (pos < NS_) sidxw[pos] = chunk + lane * 8 + j;
            pos++;
        }
    }
}

// ---------------------------------------------------------------------------
// Phase 1 (fused): blocks [0, BQ_BLOCKS) ball query; rest transpose features.
// ---------------------------------------------------------------------------
__global__ void __launch_bounds__(256) phase1_kernel(
    const float* __restrict__ xyz, const float* __restrict__ new_xyz,
    const float* __restrict__ f) {

    if (blockIdx.x < BQ_BLOCKS) {
        // ================= ball query: one warp per query ==================
        __shared__ int sidx[8][NS_];

        const int tid  = threadIdx.x;
        const int w    = tid >> 5;
        const int lane = tid & 31;
        const int q    = blockIdx.x * 8 + w;
        const int b    = q >> 10;

        const float*  xb    = xyz + (size_t)b * N_ * 3;
        const float4* base4 = (const float4*)xb;
        const float*  qp    = new_xyz + (size_t)q * 3;
        const float qx = qp[0], qy = qp[1], qz = qp[2];
        const int tfo = lane * 6;            // thread float4 offset in chunk

        int total = 0;
        BqBuf A, B;
        bq_load(base4, (0 / 4) * 3 + tfo, A);          // chunk 0
        bq_load(base4, (256 / 4) * 3 + tfo, B);        // chunk 256

        // chunk n0 starts at float 3*n0 = float4 index 3*n0/4 = (n0/4)*3
        for (int n0 = 0; n0 < N_; n0 += 512) {
            // ---- half A: chunk n0 ----
            {
                const unsigned m = bq_mask(A, qx, qy, qz);
                if (n0 + 512 < N_)
                    bq_load(base4, ((n0 + 512) >> 2) * 3 + tfo, A);
                const int cnt = __reduce_add_sync(0xffffffffu, __popc(m));
                if (cnt) {
                    if (total < NS_) bq_place(m, n0, lane, total, sidx[w]);
                    total += cnt;
                    if (total >= NS_) break;
                }
            }
            // ---- half B: chunk n0+256 ----
            {
                const unsigned m = bq_mask(B, qx, qy, qz);
                if (n0 + 768 < N_)
                    bq_load(base4, ((n0 + 768) >> 2) * 3 + tfo, B);
                const int cnt = __reduce_add_sync(0xffffffffu, __popc(m));
                if (cnt) {
                    if (total < NS_) bq_place(m, n0 + 256, lane, total, sidx[w]);
                    total += cnt;
                    if (total >= NS_) break;
                }
            }
        }

        __syncwarp();
        int v;
        if (total == 0) {
            v = N_ - 1;  // reference: all-invalid -> clamped gather
        } else {
            const int first = sidx[w][0];
            v = (lane < min(total, NS_)) ? sidx[w][lane] : first;
        }
        g_idx[(size_t)q * NS_ + lane] = v;

    } else {
        // ==== transpose features (B,C,N)->(B,N,C): 4 32x32 tiles per block ==
        __shared__ float tile[4][32][33];

        const int t  = blockIdx.x - BQ_BLOCKS;
        const int bx = t & 127;            // N/128 = 128
        const int by = (t >> 7) & 1;       // C/32  = 2
        const int bz = t >> 8;             // B
        const int c0 = by * 32;
        const int tx = threadIdx.x & 7;
        const int ty = threadIdx.x >> 3;

        const float* src = f + (size_t)bz * C_ * N_;
        float*       dst = g_ft + (size_t)bz * N_ * C_;

#pragma unroll
        for (int u = 0; u < 4; u++) {
            const int n0 = bx * 128 + u * 32;
            const float4 v =
                *(const float4*)(src + (size_t)(c0 + ty) * N_ + n0 + tx * 4);
            tile[u][ty][tx * 4 + 0] = v.x;
            tile[u][ty][tx * 4 + 1] = v.y;
            tile[u][ty][tx * 4 + 2] = v.z;
            tile[u][ty][tx * 4 + 3] = v.w;
        }
        __syncthreads();
#pragma unroll
        for (int u = 0; u < 4; u++) {
            const int n0 = bx * 128 + u * 32;
            float4 o;
            o.x = tile[u][tx * 4 + 0][ty];
            o.y = tile[u][tx * 4 + 1][ty];
            o.z = tile[u][tx * 4 + 2][ty];
            o.w = tile[u][tx * 4 + 3][ty];
            *(float4*)(dst + (size_t)(n0 + ty) * C_ + c0 + tx * 4) = o;
        }
    }
}

// ---------------------------------------------------------------------------
// Kernel 2: grouping. One block per (b, m). Gather scalar/conflict-free;
// write loop vectorized (column reads of tile are conflict-free: stride 33).
// ---------------------------------------------------------------------------
__global__ void group_kernel(const float* __restrict__ xyz,
                             const float* __restrict__ new_xyz,
                             float* __restrict__ out) {
    __shared__ int   sidx[NS_];
    __shared__ float tile[COUT_][33];

    const int bm = blockIdx.x;
    const int b  = bm >> 10;
    const int m  = bm & (M_ - 1);
    const int t  = threadIdx.x;          // 256 threads
    const int w  = t >> 5;
    const int lane = t & 31;

    if (t < NS_) sidx[t] = g_idx[(size_t)bm * NS_ + t];
    __syncthreads();

    const float* ftb = g_ft + (size_t)b * N_ * C_;
    const float* qp  = new_xyz + ((size_t)b * M_ + m) * 3;

#pragma unroll
    for (int k = 0; k < 4; k++) {
        const int s = w + k * 8;         // 8 warps cover 32 samples
        const int n = sidx[s];
        const float* col = ftb + (size_t)n * C_;
        tile[3 + lane][s]      = col[lane];
        tile[3 + 32 + lane][s] = col[lane + 32];
        if (lane < 3)
            tile[lane][s] = xyz[((size_t)b * N_ + n) * 3 + lane] - qp[lane];
    }
    __syncthreads();

    float* ob = out + ((size_t)b * COUT_ * M_ + m) * NS_;
    for (int e = t; e < COUT_ * 8; e += 256) {
        const int c  = e >> 3;
        const int s4 = (e & 7) * 4;
        float4 v;
        v.x = tile[c][s4 + 0];
        v.y = tile[c][s4 + 1];
        v.z = tile[c][s4 + 2];
        v.w = tile[c][s4 + 3];
        *(float4*)(ob + (size_t)c * (M_ * NS_) + s4) = v;
    }
}

// ---------------------------------------------------------------------------
extern "C" void kernel_launch(void* const* d_in, const int* in_sizes, int n_in,
                              void* d_out, int out_size) {
    const float* xyz = nullptr;
    const float* new_xyz = nullptr;
    const float* feats = nullptr;
    for (int i = 0; i < n_in; i++) {
        if (in_sizes[i] == B_ * N_ * 3)      xyz     = (const float*)d_in[i];
        else if (in_sizes[i] == B_ * M_ * 3) new_xyz = (const float*)d_in[i];
        else if (in_sizes[i] == B_ * C_ * N_) feats  = (const float*)d_in[i];
    }
    float* out = (float*)d_out;

    phase1_kernel<<<BQ_BLOCKS + TR_BLOCKS, 256>>>(xyz, new_xyz, feats);
    group_kernel<<<B_ * M_, 256>>>(xyz, new_xyz, out);
}